// round 14
// baseline (speedup 1.0000x reference)
#include <cuda_runtime.h>
#include <cuda_bf16.h>
#include <cstdint>

// Problem constants
#define B_   8
#define T_   4096
#define E_   1024
#define H_   16
#define L_   64
#define HD_  64
#define NBLK (T_ / L_)        // 64 blocks per sequence
#define M_   (B_ * T_)        // 32768 rows
#define N1_  (3 * E_)         // 3072

// Scratch (static device arrays: allowed; cudaMalloc is not)
__device__ float g_qkv[(size_t)M_ * N1_];                 // fp32 qkv (attention input)
__device__ __nv_bfloat16 g_xhi[(size_t)M_ * E_];          // x split
__device__ __nv_bfloat16 g_xlo[(size_t)M_ * E_];
__device__ __nv_bfloat16 g_ahi[(size_t)M_ * E_];          // attention output split
__device__ __nv_bfloat16 g_alo[(size_t)M_ * E_];
__device__ __nv_bfloat16 g_w1hi[(size_t)N1_ * E_];        // Wqkv split
__device__ __nv_bfloat16 g_w1lo[(size_t)N1_ * E_];
__device__ __nv_bfloat16 g_w2hi[(size_t)E_ * E_];         // Wout split
__device__ __nv_bfloat16 g_w2lo[(size_t)E_ * E_];

// ---------------------------------------------------------------------------
// Helpers
// ---------------------------------------------------------------------------
__device__ __forceinline__ uint32_t smem_u32(const void* p) {
    uint32_t a;
    asm("{ .reg .u64 t; cvta.to.shared.u64 t, %1; cvt.u32.u64 %0, t; }"
        : "=r"(a) : "l"(p));
    return a;
}

__device__ __forceinline__ void ldsm4(uint32_t* r, uint32_t addr) {
    asm volatile("ldmatrix.sync.aligned.m8n8.x4.shared.b16 {%0,%1,%2,%3}, [%4];"
                 : "=r"(r[0]), "=r"(r[1]), "=r"(r[2]), "=r"(r[3])
                 : "r"(addr));
}

__device__ __forceinline__ void mma16816(float* c, const uint32_t* a,
                                         const uint32_t* b) {
    asm volatile(
        "mma.sync.aligned.m16n8k16.row.col.f32.bf16.bf16.f32 "
        "{%0,%1,%2,%3}, {%4,%5,%6,%7}, {%8,%9}, {%0,%1,%2,%3};"
        : "+f"(c[0]), "+f"(c[1]), "+f"(c[2]), "+f"(c[3])
        : "r"(a[0]), "r"(a[1]), "r"(a[2]), "r"(a[3]),
          "r"(b[0]), "r"(b[1]));
}

__device__ __forceinline__ void cp16(uint32_t dst, const void* src) {
    asm volatile("cp.async.cg.shared.global [%0], [%1], 16;"
                 :: "r"(dst), "l"(src) : "memory");
}
#define CP_COMMIT() asm volatile("cp.async.commit_group;" ::: "memory")
#define CP_WAIT2()  asm volatile("cp.async.wait_group 2;" ::: "memory")

// Split 4 fp32 -> bf16 hi (uint2) + bf16 lo (uint2)
__device__ __forceinline__ void split4(const float* v, uint2& hw, uint2& lw) {
    __nv_bfloat162 h0 = __floats2bfloat162_rn(v[0], v[1]);
    __nv_bfloat162 h1 = __floats2bfloat162_rn(v[2], v[3]);
    float2 f0 = __bfloat1622float2(h0);
    float2 f1 = __bfloat1622float2(h1);
    __nv_bfloat162 l0 = __floats2bfloat162_rn(v[0] - f0.x, v[1] - f0.y);
    __nv_bfloat162 l1 = __floats2bfloat162_rn(v[2] - f1.x, v[3] - f1.y);
    hw.x = *reinterpret_cast<uint32_t*>(&h0);
    hw.y = *reinterpret_cast<uint32_t*>(&h1);
    lw.x = *reinterpret_cast<uint32_t*>(&l0);
    lw.y = *reinterpret_cast<uint32_t*>(&l1);
}

// ---------------------------------------------------------------------------
// Elementwise fp32 -> bf16 hi/lo split
// ---------------------------------------------------------------------------
__global__ __launch_bounds__(256)
void split_fp32(const float4* __restrict__ src, uint2* __restrict__ hi,
                uint2* __restrict__ lo, int n4)
{
    int i = blockIdx.x * blockDim.x + threadIdx.x;
    if (i >= n4) return;
    float4 v = src[i];
    float a[4] = {v.x, v.y, v.z, v.w};
    uint2 hw, lw;
    split4(a, hw, lw);
    hi[i] = hw;
    lo[i] = lw;
}

// ---------------------------------------------------------------------------
// Split-bf16 tensor-core GEMM: C[M,N] = (Ahi+Alo)[M,K] @ (Bhi+Blo)[N,K]^T + bias
// CTA tile 128x128, BK=32, 256 threads (8 warps, 4M x 2N), 4-stage cp.async.
// smem stage: Ahi|Alo|Bhi|Blo, each 128 rows x pitch 80B (64B data + 16B pad).
// ---------------------------------------------------------------------------
#define GBM 128
#define GBN 128
#define GBK 32
#define PITCH 80
#define SEG  10240                   // 128 * 80
#define STAGE (4 * SEG)              // 40960
#define NSTAGE 4
#define GEMM_SMEM (NSTAGE * STAGE)   // 163840

__device__ __forceinline__ void load_chunk(
    uint32_t stageAddr, const __nv_bfloat16* aH, const __nv_bfloat16* aL,
    const __nv_bfloat16* bH, const __nv_bfloat16* bL,
    int tid, int K, int kOff)
{
#pragma unroll
    for (int i = 0; i < 2; i++) {
        int idx = tid + i * 256;
        int row = idx >> 2, col = idx & 3;
        uint32_t off = (uint32_t)row * PITCH + col * 16;
        long s = (long)row * K + kOff + col * 8;
        cp16(stageAddr + off,           aH + s);
        cp16(stageAddr + SEG + off,     aL + s);
        cp16(stageAddr + 2 * SEG + off, bH + s);
        cp16(stageAddr + 3 * SEG + off, bL + s);
    }
}

__global__ __launch_bounds__(256, 1)
void gemm_tc(const __nv_bfloat16* __restrict__ Ahi,
             const __nv_bfloat16* __restrict__ Alo,
             const __nv_bfloat16* __restrict__ Bhi,
             const __nv_bfloat16* __restrict__ Blo,
             const float* __restrict__ bias, float* __restrict__ C,
             int N, int K)
{
    extern __shared__ char smem[];

    const int tid  = threadIdx.x;
    const int wid  = tid >> 5;
    const int lane = tid & 31;
    const int wm   = wid & 3;
    const int wn   = wid >> 2;

    const long mBase = (long)blockIdx.y * GBM;
    const long nBase = (long)blockIdx.x * GBN;
    const __nv_bfloat16* aH = Ahi + mBase * K;
    const __nv_bfloat16* aL = Alo + mBase * K;
    const __nv_bfloat16* bH = Bhi + nBase * K;
    const __nv_bfloat16* bL = Blo + nBase * K;

    float acc[2][8][4];
#pragma unroll
    for (int mt = 0; mt < 2; mt++)
#pragma unroll
        for (int nt = 0; nt < 8; nt++)
#pragma unroll
            for (int i = 0; i < 4; i++) acc[mt][nt][i] = 0.0f;

    // ldmatrix lane-resolved offsets (same fragment mapping as round 12)
    const uint32_t aRow  = (((lane >> 3) & 1) * 8) + (lane & 7);
    const uint32_t aKoff = (lane >> 4) * 16;
    const uint32_t bRow  = ((lane >> 4) * 8) + (lane & 7);
    const uint32_t bKoff = ((lane >> 3) & 1) * 16;

    const uint32_t smemBase = smem_u32(smem);
    const int NC = K / GBK;

    // Prologue: stages 0..2 in flight
#pragma unroll
    for (int c = 0; c < 3; c++) {
        load_chunk(smemBase + c * STAGE, aH, aL, bH, bL, tid, K, c * GBK);
        CP_COMMIT();
    }
    CP_WAIT2();          // group 0 complete
    __syncthreads();

    for (int c = 0; c < NC; c++) {
        const uint32_t stage = smemBase + (c & 3) * STAGE;
        const uint32_t aHiB = stage           + (wm * 32 + aRow) * PITCH + aKoff;
        const uint32_t aLoB = stage + SEG     + (wm * 32 + aRow) * PITCH + aKoff;
        const uint32_t bHiB = stage + 2 * SEG + (wn * 64 + bRow) * PITCH + bKoff;
        const uint32_t bLoB = stage + 3 * SEG + (wn * 64 + bRow) * PITCH + bKoff;

#pragma unroll
        for (int ks = 0; ks < 2; ks++) {
            uint32_t ahi[2][4], alo[2][4], bhi[4][4], blo[4][4];
#pragma unroll
            for (int mt = 0; mt < 2; mt++) {
                ldsm4(ahi[mt], aHiB + mt * 16 * PITCH + ks * 32);
                ldsm4(alo[mt], aLoB + mt * 16 * PITCH + ks * 32);
            }
#pragma unroll
            for (int np = 0; np < 4; np++) {
                ldsm4(bhi[np], bHiB + np * 16 * PITCH + ks * 32);
                ldsm4(blo[np], bLoB + np * 16 * PITCH + ks * 32);
            }
#pragma unroll
            for (int mt = 0; mt < 2; mt++)
#pragma unroll
                for (int nt = 0; nt < 8; nt++) {
                    const uint32_t* bhp = &bhi[nt >> 1][(nt & 1) * 2];
                    const uint32_t* blp = &blo[nt >> 1][(nt & 1) * 2];
                    mma16816(acc[mt][nt], ahi[mt], bhp);   // hi*hi
                    mma16816(acc[mt][nt], ahi[mt], blp);   // hi*lo
                    mma16816(acc[mt][nt], alo[mt], bhp);   // lo*hi
                }
        }

        // Issue next loads; always commit (possibly empty group) so the
        // wait_group accounting stays uniform through the tail.
        if (c + 3 < NC)
            load_chunk(smemBase + ((c + 3) & 3) * STAGE, aH, aL, bH, bL,
                       tid, K, (c + 3) * GBK);
        CP_COMMIT();
        CP_WAIT2();      // committed = c+4 -> groups <= c+1 complete
        __syncthreads();
    }

    // Epilogue: acc + bias -> C (standard m16n8 fragment layout)
    const int g  = lane >> 2;
    const int tg = lane & 3;
    const long wRow = mBase + wm * 32 + g;
    const long wCol = nBase + wn * 64 + tg * 2;

    float2 bfrag[8];
#pragma unroll
    for (int nt = 0; nt < 8; nt++)
        bfrag[nt] = *(const float2*)(bias + wCol + nt * 8);

#pragma unroll
    for (int mt = 0; mt < 2; mt++) {
        long r0 = wRow + mt * 16;
#pragma unroll
        for (int nt = 0; nt < 8; nt++) {
            float2 o0, o1;
            o0.x = acc[mt][nt][0] + bfrag[nt].x;
            o0.y = acc[mt][nt][1] + bfrag[nt].y;
            o1.x = acc[mt][nt][2] + bfrag[nt].x;
            o1.y = acc[mt][nt][3] + bfrag[nt].y;
            *(float2*)(C + r0 * N + wCol + nt * 8)       = o0;
            *(float2*)(C + (r0 + 8) * N + wCol + nt * 8) = o1;
        }
    }
}

// ---------------------------------------------------------------------------
// Local block attention: fp32 compute, split-bf16 output stores.
// ---------------------------------------------------------------------------
__global__ __launch_bounds__(256)
void local_attn(const float* __restrict__ qkv,
                __nv_bfloat16* __restrict__ outHi,
                __nv_bfloat16* __restrict__ outLo)
{
    __shared__ float bufA[L_][HD_ + 1];
    __shared__ float bufB[L_][HD_ + 1];

    const int bid = blockIdx.x;
    const int n = bid % NBLK;
    const int h = (bid / NBLK) % H_;
    const int b = bid / (NBLK * H_);
    const int tid = threadIdx.x;

    const long rowBase = (long)b * T_ + (long)n * L_;
    const int l  = tid >> 2;
    const int c0 = (tid & 3) * 16;
    const float scale = 0.125f;

    const float* qp = qkv + (rowBase + l) * (long)N1_ + h * HD_;

#pragma unroll
    for (int j = 0; j < 16; j += 4) {
        float4 q4 = *(const float4*)(qp + c0 + j);
        bufA[l][c0 + j + 0] = q4.x * scale;
        bufA[l][c0 + j + 1] = q4.y * scale;
        bufA[l][c0 + j + 2] = q4.z * scale;
        bufA[l][c0 + j + 3] = q4.w * scale;
        float4 k4 = *(const float4*)(qp + E_ + c0 + j);
        bufB[c0 + j + 0][l] = k4.x;
        bufB[c0 + j + 1][l] = k4.y;
        bufB[c0 + j + 2][l] = k4.z;
        bufB[c0 + j + 3][l] = k4.w;
    }
    __syncthreads();

    float s[16];
#pragma unroll
    for (int j = 0; j < 16; j++) s[j] = 0.0f;
    for (int d = 0; d < HD_; d++) {
        float qv = bufA[l][d];
#pragma unroll
        for (int j = 0; j < 16; j++)
            s[j] += qv * bufB[d][c0 + j];
    }
    __syncthreads();

#pragma unroll
    for (int j = 0; j < 16; j++) bufA[l][c0 + j] = s[j];
#pragma unroll
    for (int j = 0; j < 16; j += 4) {
        float4 v4 = *(const float4*)(qp + 2 * E_ + c0 + j);
        bufB[l][c0 + j + 0] = v4.x;
        bufB[l][c0 + j + 1] = v4.y;
        bufB[l][c0 + j + 2] = v4.z;
        bufB[l][c0 + j + 3] = v4.w;
    }
    __syncthreads();

    const int wid = tid >> 5, lane = tid & 31;
#pragma unroll
    for (int rr = 0; rr < 8; rr++) {
        int r = wid * 8 + rr;
        float v0 = bufA[r][lane];
        float v1 = bufA[r][lane + 32];
        float mx = fmaxf(v0, v1);
#pragma unroll
        for (int o = 16; o > 0; o >>= 1)
            mx = fmaxf(mx, __shfl_xor_sync(0xffffffffu, mx, o));
        float e0 = __expf(v0 - mx);
        float e1 = __expf(v1 - mx);
        float sm = e0 + e1;
#pragma unroll
        for (int o = 16; o > 0; o >>= 1)
            sm += __shfl_xor_sync(0xffffffffu, sm, o);
        float inv = 1.0f / sm;
        bufA[r][lane]      = e0 * inv;
        bufA[r][lane + 32] = e1 * inv;
    }
    __syncthreads();

    float o[16];
#pragma unroll
    for (int j = 0; j < 16; j++) o[j] = 0.0f;
    for (int m = 0; m < L_; m++) {
        float p = bufA[l][m];
#pragma unroll
        for (int j = 0; j < 16; j++)
            o[j] += p * bufB[m][c0 + j];
    }

    const long oBase = (rowBase + l) * (long)E_ + h * HD_ + c0;
#pragma unroll
    for (int j = 0; j < 16; j += 4) {
        uint2 hw, lw;
        split4(&o[j], hw, lw);
        *reinterpret_cast<uint2*>(outHi + oBase + j) = hw;
        *reinterpret_cast<uint2*>(outLo + oBase + j) = lw;
    }
}

// ---------------------------------------------------------------------------
// Launch
// ---------------------------------------------------------------------------
extern "C" void kernel_launch(void* const* d_in, const int* in_sizes, int n_in,
                              void* d_out, int out_size)
{
    const float* x    = (const float*)d_in[0];
    const float* Wqkv = (const float*)d_in[1];
    const float* bqkv = (const float*)d_in[2];
    const float* Wout = (const float*)d_in[3];
    const float* bout = (const float*)d_in[4];
    float* out = (float*)d_out;

    void* p;
    cudaGetSymbolAddress(&p, g_qkv);  float* qkv = (float*)p;
    cudaGetSymbolAddress(&p, g_xhi);  __nv_bfloat16* xhi = (__nv_bfloat16*)p;
    cudaGetSymbolAddress(&p, g_xlo);  __nv_bfloat16* xlo = (__nv_bfloat16*)p;
    cudaGetSymbolAddress(&p, g_ahi);  __nv_bfloat16* ahi = (__nv_bfloat16*)p;
    cudaGetSymbolAddress(&p, g_alo);  __nv_bfloat16* alo = (__nv_bfloat16*)p;
    cudaGetSymbolAddress(&p, g_w1hi); __nv_bfloat16* w1hi = (__nv_bfloat16*)p;
    cudaGetSymbolAddress(&p, g_w1lo); __nv_bfloat16* w1lo = (__nv_bfloat16*)p;
    cudaGetSymbolAddress(&p, g_w2hi); __nv_bfloat16* w2hi = (__nv_bfloat16*)p;
    cudaGetSymbolAddress(&p, g_w2lo); __nv_bfloat16* w2lo = (__nv_bfloat16*)p;

    cudaFuncSetAttribute(gemm_tc, cudaFuncAttributeMaxDynamicSharedMemorySize,
                         GEMM_SMEM);

    // Split inputs to bf16 hi/lo
    {
        int n4 = M_ * E_ / 4;
        split_fp32<<<(n4 + 255) / 256, 256>>>((const float4*)x,
                                              (uint2*)xhi, (uint2*)xlo, n4);
        n4 = N1_ * E_ / 4;
        split_fp32<<<(n4 + 255) / 256, 256>>>((const float4*)Wqkv,
                                              (uint2*)w1hi, (uint2*)w1lo, n4);
        n4 = E_ * E_ / 4;
        split_fp32<<<(n4 + 255) / 256, 256>>>((const float4*)Wout,
                                              (uint2*)w2hi, (uint2*)w2lo, n4);
    }

    // GEMM1: qkv = x @ Wqkv^T + bqkv  (32768 x 3072 x 1024)
    gemm_tc<<<dim3(N1_ / GBN, M_ / GBM), 256, GEMM_SMEM>>>(
        xhi, xlo, w1hi, w1lo, bqkv, qkv, N1_, E_);

    // Local block attention -> split bf16 output
    local_attn<<<B_ * H_ * NBLK, 256>>>(qkv, ahi, alo);

    // GEMM2: out = att @ Wout^T + bout (32768 x 1024 x 1024)
    gemm_tc<<<dim3(E_ / GBN, M_ / GBM), 256, GEMM_SMEM>>>(
        ahi, alo, w2hi, w2lo, bout, out, E_, E_);
}

// round 15
// speedup vs baseline: 1.5842x; 1.5842x over previous
#include <cuda_runtime.h>
#include <cuda_bf16.h>
#include <cstdint>

// Problem constants
#define B_   8
#define T_   4096
#define E_   1024
#define H_   16
#define L_   64
#define HD_  64
#define NBLK (T_ / L_)        // 64 blocks per sequence
#define M_   (B_ * T_)        // 32768 rows
#define N1_  (3 * E_)         // 3072

// Scratch (static device arrays: allowed; cudaMalloc is not)
__device__ float g_qkv[(size_t)M_ * N1_];                 // fp32 qkv (attention input)
__device__ __nv_bfloat16 g_xhi[(size_t)M_ * E_];
__device__ __nv_bfloat16 g_xlo[(size_t)M_ * E_];
__device__ __nv_bfloat16 g_ahi[(size_t)M_ * E_];
__device__ __nv_bfloat16 g_alo[(size_t)M_ * E_];
__device__ __nv_bfloat16 g_w1hi[(size_t)N1_ * E_];
__device__ __nv_bfloat16 g_w1lo[(size_t)N1_ * E_];
__device__ __nv_bfloat16 g_w2hi[(size_t)E_ * E_];
__device__ __nv_bfloat16 g_w2lo[(size_t)E_ * E_];

// ---------------------------------------------------------------------------
// Helpers
// ---------------------------------------------------------------------------
__device__ __forceinline__ uint32_t smem_u32(const void* p) {
    uint32_t a;
    asm("{ .reg .u64 t; cvta.to.shared.u64 t, %1; cvt.u32.u64 %0, t; }"
        : "=r"(a) : "l"(p));
    return a;
}

__device__ __forceinline__ void ldsm4(uint32_t* r, uint32_t addr) {
    asm volatile("ldmatrix.sync.aligned.m8n8.x4.shared.b16 {%0,%1,%2,%3}, [%4];"
                 : "=r"(r[0]), "=r"(r[1]), "=r"(r[2]), "=r"(r[3])
                 : "r"(addr));
}

__device__ __forceinline__ void mma16816(float* c, const uint32_t* a,
                                         const uint32_t* b) {
    asm volatile(
        "mma.sync.aligned.m16n8k16.row.col.f32.bf16.bf16.f32 "
        "{%0,%1,%2,%3}, {%4,%5,%6,%7}, {%8,%9}, {%0,%1,%2,%3};"
        : "+f"(c[0]), "+f"(c[1]), "+f"(c[2]), "+f"(c[3])
        : "r"(a[0]), "r"(a[1]), "r"(a[2]), "r"(a[3]),
          "r"(b[0]), "r"(b[1]));
}

__device__ __forceinline__ void cp16(uint32_t dst, const void* src) {
    asm volatile("cp.async.cg.shared.global [%0], [%1], 16;"
                 :: "r"(dst), "l"(src) : "memory");
}
#define CP_COMMIT() asm volatile("cp.async.commit_group;" ::: "memory")
#define CP_WAIT1()  asm volatile("cp.async.wait_group 1;" ::: "memory")

// Split 4 fp32 -> bf16 hi (uint2) + bf16 lo (uint2)
__device__ __forceinline__ void split4(const float* v, uint2& hw, uint2& lw) {
    __nv_bfloat162 h0 = __floats2bfloat162_rn(v[0], v[1]);
    __nv_bfloat162 h1 = __floats2bfloat162_rn(v[2], v[3]);
    float2 f0 = __bfloat1622float2(h0);
    float2 f1 = __bfloat1622float2(h1);
    __nv_bfloat162 l0 = __floats2bfloat162_rn(v[0] - f0.x, v[1] - f0.y);
    __nv_bfloat162 l1 = __floats2bfloat162_rn(v[2] - f1.x, v[3] - f1.y);
    hw.x = *reinterpret_cast<uint32_t*>(&h0);
    hw.y = *reinterpret_cast<uint32_t*>(&h1);
    lw.x = *reinterpret_cast<uint32_t*>(&l0);
    lw.y = *reinterpret_cast<uint32_t*>(&l1);
}

// ---------------------------------------------------------------------------
// Elementwise fp32 -> bf16 hi/lo split
// ---------------------------------------------------------------------------
__global__ __launch_bounds__(256)
void split_fp32(const float4* __restrict__ src, uint2* __restrict__ hi,
                uint2* __restrict__ lo, int n4)
{
    int i = blockIdx.x * blockDim.x + threadIdx.x;
    if (i >= n4) return;
    float4 v = src[i];
    float a[4] = {v.x, v.y, v.z, v.w};
    uint2 hw, lw;
    split4(a, hw, lw);
    hi[i] = hw;
    lo[i] = lw;
}

// ---------------------------------------------------------------------------
// Split-bf16 tensor-core GEMM: C[M,N] = (Ahi+Alo) @ (Bhi+Blo)^T + bias
// CTA tile 128x128, BK=32, 256 threads (8 warps, 4M x 2N), 3-stage cp.async,
// 2 CTAs/SM. Packed smem: 64B rows, 16B-chunk XOR swizzle c^((row>>1)&3)
// (conflict-free for ldmatrix: granule index (4*row + c') mod 8 distinct
// across each 8-row matrix).
// Stage = Ahi|Alo|Bhi|Blo, each 128*64B = 8192B -> 32768B; 3 stages = 98304B.
// ---------------------------------------------------------------------------
#define GBM 128
#define GBN 128
#define GBK 32
#define SEG  8192
#define STAGE (4 * SEG)              // 32768
#define NSTAGE 3
#define GEMM_SMEM (NSTAGE * STAGE)   // 98304

__device__ __forceinline__ uint32_t swz(uint32_t row, uint32_t chunk) {
    return row * 64 + ((chunk ^ ((row >> 1) & 3)) << 4);
}

__device__ __forceinline__ void load_chunk(
    uint32_t stageAddr, const __nv_bfloat16* aH, const __nv_bfloat16* aL,
    const __nv_bfloat16* bH, const __nv_bfloat16* bL,
    int tid, int K, int kOff)
{
#pragma unroll
    for (int i = 0; i < 2; i++) {
        int idx = tid + i * 256;
        uint32_t row = idx >> 2, ch = idx & 3;
        uint32_t off = swz(row, ch);
        long s = (long)row * K + kOff + ch * 8;
        cp16(stageAddr + off,           aH + s);
        cp16(stageAddr + SEG + off,     aL + s);
        cp16(stageAddr + 2 * SEG + off, bH + s);
        cp16(stageAddr + 3 * SEG + off, bL + s);
    }
}

__global__ __launch_bounds__(256, 2)
void gemm_tc(const __nv_bfloat16* __restrict__ Ahi,
             const __nv_bfloat16* __restrict__ Alo,
             const __nv_bfloat16* __restrict__ Bhi,
             const __nv_bfloat16* __restrict__ Blo,
             const float* __restrict__ bias, float* __restrict__ C,
             int N, int K)
{
    extern __shared__ char smem[];

    const int tid  = threadIdx.x;
    const int wid  = tid >> 5;
    const int lane = tid & 31;
    const int wm   = wid & 3;
    const int wn   = wid >> 2;

    const long mBase = (long)blockIdx.y * GBM;
    const long nBase = (long)blockIdx.x * GBN;
    const __nv_bfloat16* aH = Ahi + mBase * K;
    const __nv_bfloat16* aL = Alo + mBase * K;
    const __nv_bfloat16* bH = Bhi + nBase * K;
    const __nv_bfloat16* bL = Blo + nBase * K;

    float acc[2][8][4];
#pragma unroll
    for (int mt = 0; mt < 2; mt++)
#pragma unroll
        for (int nt = 0; nt < 8; nt++)
#pragma unroll
            for (int i = 0; i < 4; i++) acc[mt][nt][i] = 0.0f;

    // Fragment lane mapping (same as before):
    // A x4 quads: [r0-7 klo, r8-15 klo, r0-7 khi, r8-15 khi]
    const uint32_t aRow = (((lane >> 3) & 1) * 8) + (lane & 7);  // 0..15
    const uint32_t aKch = (lane >> 4);                           // 0/1 (16B chunk)
    // B x4 quads: [n0-7 klo, n0-7 khi, n8-15 klo, n8-15 khi]
    const uint32_t bRow = ((lane >> 4) * 8) + (lane & 7);        // 0..15
    const uint32_t bKch = ((lane >> 3) & 1);                     // 0/1

    const uint32_t smemBase = smem_u32(smem);
    const int NC = K / GBK;

    // Prologue: chunks 0,1 in flight
    load_chunk(smemBase,         aH, aL, bH, bL, tid, K, 0);
    CP_COMMIT();
    load_chunk(smemBase + STAGE, aH, aL, bH, bL, tid, K, GBK);
    CP_COMMIT();

    int stageIdx = 0;
    for (int c = 0; c < NC; c++) {
        CP_WAIT1();              // group c complete (c+1 may be in flight)
        __syncthreads();

        const uint32_t stage = smemBase + stageIdx * STAGE;

#pragma unroll
        for (int ks = 0; ks < 2; ks++) {
            // A fragments (hi+lo) for this k16 step
            uint32_t ahi[2][4], alo[2][4];
#pragma unroll
            for (int mt = 0; mt < 2; mt++) {
                uint32_t row = wm * 32 + mt * 16 + aRow;
                uint32_t off = swz(row, ks * 2 + aKch);
                ldsm4(ahi[mt], stage + off);
                ldsm4(alo[mt], stage + SEG + off);
            }
#pragma unroll
            for (int np = 0; np < 4; np++) {
                uint32_t row = wn * 64 + np * 16 + bRow;
                uint32_t off = swz(row, ks * 2 + bKch);
                uint32_t bhi[4], blo[4];
                ldsm4(bhi, stage + 2 * SEG + off);
                ldsm4(blo, stage + 3 * SEG + off);
#pragma unroll
                for (int mt = 0; mt < 2; mt++)
#pragma unroll
                    for (int sub = 0; sub < 2; sub++) {
                        float* a4 = acc[mt][np * 2 + sub];
                        mma16816(a4, ahi[mt], &bhi[sub * 2]);  // hi*hi
                        mma16816(a4, ahi[mt], &blo[sub * 2]);  // hi*lo
                        mma16816(a4, alo[mt], &bhi[sub * 2]);  // lo*hi
                    }
            }
        }

        // Prefetch chunk c+2 into the stage last read at iteration c-1
        // (all its readers passed this iteration's __syncthreads).
        if (c + 2 < NC) {
            int ns = stageIdx + 2;
            if (ns >= NSTAGE) ns -= NSTAGE;
            load_chunk(smemBase + ns * STAGE, aH, aL, bH, bL,
                       tid, K, (c + 2) * GBK);
        }
        CP_COMMIT();             // commit every iter (uniform accounting)

        if (++stageIdx == NSTAGE) stageIdx = 0;
    }

    // Epilogue: acc + bias -> C (standard m16n8 fragment layout)
    const int g  = lane >> 2;
    const int tg = lane & 3;
    const long wRow = mBase + wm * 32 + g;
    const long wCol = nBase + wn * 64 + tg * 2;

#pragma unroll
    for (int mt = 0; mt < 2; mt++) {
        long r0 = wRow + mt * 16;
#pragma unroll
        for (int nt = 0; nt < 8; nt++) {
            float2 bf = *(const float2*)(bias + wCol + nt * 8);
            float2 o0, o1;
            o0.x = acc[mt][nt][0] + bf.x;
            o0.y = acc[mt][nt][1] + bf.y;
            o1.x = acc[mt][nt][2] + bf.x;
            o1.y = acc[mt][nt][3] + bf.y;
            *(float2*)(C + r0 * N + wCol + nt * 8)       = o0;
            *(float2*)(C + (r0 + 8) * N + wCol + nt * 8) = o1;
        }
    }
}

// ---------------------------------------------------------------------------
// Local block attention: fp32 compute, 4x4 microtiles (0.5 LDS/FMA),
// split-bf16 output stores.
// ---------------------------------------------------------------------------
__global__ __launch_bounds__(256)
void local_attn(const float* __restrict__ qkv,
                __nv_bfloat16* __restrict__ outHi,
                __nv_bfloat16* __restrict__ outLo)
{
    __shared__ float bufA[L_][HD_ + 1];   // q / S / P
    __shared__ float bufB[L_][HD_ + 1];   // k^T, then v

    const int bid = blockIdx.x;
    const int n = bid % NBLK;
    const int h = (bid / NBLK) % H_;
    const int b = bid / (NBLK * H_);
    const int tid = threadIdx.x;

    const long rowBase = (long)b * T_ + (long)n * L_;
    const int l  = tid >> 2;              // 0..63 (load mapping)
    const int c0 = (tid & 3) * 16;
    const float scale = 0.125f;

    const int tr = (tid >> 4) * 4;        // microtile row base 0..60
    const int tc = (tid & 15) * 4;        // microtile col base 0..60

    const float* qp = qkv + (rowBase + l) * (long)N1_ + h * HD_;

#pragma unroll
    for (int j = 0; j < 16; j += 4) {
        float4 q4 = *(const float4*)(qp + c0 + j);
        bufA[l][c0 + j + 0] = q4.x * scale;
        bufA[l][c0 + j + 1] = q4.y * scale;
        bufA[l][c0 + j + 2] = q4.z * scale;
        bufA[l][c0 + j + 3] = q4.w * scale;
        float4 k4 = *(const float4*)(qp + E_ + c0 + j);
        bufB[c0 + j + 0][l] = k4.x;
        bufB[c0 + j + 1][l] = k4.y;
        bufB[c0 + j + 2][l] = k4.z;
        bufB[c0 + j + 3][l] = k4.w;
    }
    __syncthreads();

    // S[tr+i][tc+j] = sum_d q[tr+i][d] * kT[d][tc+j]
    float s[4][4];
#pragma unroll
    for (int i = 0; i < 4; i++)
#pragma unroll
        for (int j = 0; j < 4; j++) s[i][j] = 0.0f;
    for (int d = 0; d < HD_; d++) {
        float qv[4], kv[4];
#pragma unroll
        for (int i = 0; i < 4; i++) qv[i] = bufA[tr + i][d];
#pragma unroll
        for (int j = 0; j < 4; j++) kv[j] = bufB[d][tc + j];
#pragma unroll
        for (int i = 0; i < 4; i++)
#pragma unroll
            for (int j = 0; j < 4; j++)
                s[i][j] += qv[i] * kv[j];
    }
    __syncthreads();

    // Write S into bufA; load v into bufB (natural [m][d]).
#pragma unroll
    for (int i = 0; i < 4; i++)
#pragma unroll
        for (int j = 0; j < 4; j++)
            bufA[tr + i][tc + j] = s[i][j];
#pragma unroll
    for (int j = 0; j < 16; j += 4) {
        float4 v4 = *(const float4*)(qp + 2 * E_ + c0 + j);
        bufB[l][c0 + j + 0] = v4.x;
        bufB[l][c0 + j + 1] = v4.y;
        bufB[l][c0 + j + 2] = v4.z;
        bufB[l][c0 + j + 3] = v4.w;
    }
    __syncthreads();

    // Row softmax: warp w -> rows w*8..w*8+7, lane covers 2 columns.
    const int wid = tid >> 5, lane = tid & 31;
#pragma unroll
    for (int rr = 0; rr < 8; rr++) {
        int r = wid * 8 + rr;
        float v0 = bufA[r][lane];
        float v1 = bufA[r][lane + 32];
        float mx = fmaxf(v0, v1);
#pragma unroll
        for (int o = 16; o > 0; o >>= 1)
            mx = fmaxf(mx, __shfl_xor_sync(0xffffffffu, mx, o));
        float e0 = __expf(v0 - mx);
        float e1 = __expf(v1 - mx);
        float sm = e0 + e1;
#pragma unroll
        for (int o = 16; o > 0; o >>= 1)
            sm += __shfl_xor_sync(0xffffffffu, sm, o);
        float inv = 1.0f / sm;
        bufA[r][lane]      = e0 * inv;
        bufA[r][lane + 32] = e1 * inv;
    }
    __syncthreads();

    // O[tr+i][tc+j] = sum_m P[tr+i][m] * v[m][tc+j]
    float o[4][4];
#pragma unroll
    for (int i = 0; i < 4; i++)
#pragma unroll
        for (int j = 0; j < 4; j++) o[i][j] = 0.0f;
    for (int m = 0; m < L_; m++) {
        float pv[4], vv[4];
#pragma unroll
        for (int i = 0; i < 4; i++) pv[i] = bufA[tr + i][m];
#pragma unroll
        for (int j = 0; j < 4; j++) vv[j] = bufB[m][tc + j];
#pragma unroll
        for (int i = 0; i < 4; i++)
#pragma unroll
            for (int j = 0; j < 4; j++)
                o[i][j] += pv[i] * vv[j];
    }

#pragma unroll
    for (int i = 0; i < 4; i++) {
        const long oBase = (rowBase + tr + i) * (long)E_ + h * HD_ + tc;
        uint2 hw, lw;
        split4(o[i], hw, lw);
        *reinterpret_cast<uint2*>(outHi + oBase) = hw;
        *reinterpret_cast<uint2*>(outLo + oBase) = lw;
    }
}

// ---------------------------------------------------------------------------
// Launch
// ---------------------------------------------------------------------------
extern "C" void kernel_launch(void* const* d_in, const int* in_sizes, int n_in,
                              void* d_out, int out_size)
{
    const float* x    = (const float*)d_in[0];
    const float* Wqkv = (const float*)d_in[1];
    const float* bqkv = (const float*)d_in[2];
    const float* Wout = (const float*)d_in[3];
    const float* bout = (const float*)d_in[4];
    float* out = (float*)d_out;

    void* p;
    cudaGetSymbolAddress(&p, g_qkv);  float* qkv = (float*)p;
    cudaGetSymbolAddress(&p, g_xhi);  __nv_bfloat16* xhi = (__nv_bfloat16*)p;
    cudaGetSymbolAddress(&p, g_xlo);  __nv_bfloat16* xlo = (__nv_bfloat16*)p;
    cudaGetSymbolAddress(&p, g_ahi);  __nv_bfloat16* ahi = (__nv_bfloat16*)p;
    cudaGetSymbolAddress(&p, g_alo);  __nv_bfloat16* alo = (__nv_bfloat16*)p;
    cudaGetSymbolAddress(&p, g_w1hi); __nv_bfloat16* w1hi = (__nv_bfloat16*)p;
    cudaGetSymbolAddress(&p, g_w1lo); __nv_bfloat16* w1lo = (__nv_bfloat16*)p;
    cudaGetSymbolAddress(&p, g_w2hi); __nv_bfloat16* w2hi = (__nv_bfloat16*)p;
    cudaGetSymbolAddress(&p, g_w2lo); __nv_bfloat16* w2lo = (__nv_bfloat16*)p;

    cudaFuncSetAttribute(gemm_tc, cudaFuncAttributeMaxDynamicSharedMemorySize,
                         GEMM_SMEM);

    // Split inputs to bf16 hi/lo
    {
        int n4 = M_ * E_ / 4;
        split_fp32<<<(n4 + 255) / 256, 256>>>((const float4*)x,
                                              (uint2*)xhi, (uint2*)xlo, n4);
        n4 = N1_ * E_ / 4;
        split_fp32<<<(n4 + 255) / 256, 256>>>((const float4*)Wqkv,
                                              (uint2*)w1hi, (uint2*)w1lo, n4);
        n4 = E_ * E_ / 4;
        split_fp32<<<(n4 + 255) / 256, 256>>>((const float4*)Wout,
                                              (uint2*)w2hi, (uint2*)w2lo, n4);
    }

    // GEMM1: qkv = x @ Wqkv^T + bqkv  (32768 x 3072 x 1024)
    gemm_tc<<<dim3(N1_ / GBN, M_ / GBM), 256, GEMM_SMEM>>>(
        xhi, xlo, w1hi, w1lo, bqkv, qkv, N1_, E_);

    // Local block attention -> split bf16 output
    local_attn<<<B_ * H_ * NBLK, 256>>>(qkv, ahi, alo);

    // GEMM2: out = att @ Wout^T + bout (32768 x 1024 x 1024)
    gemm_tc<<<dim3(E_ / GBN, M_ / GBM), 256, GEMM_SMEM>>>(
        ahi, alo, w2hi, w2lo, bout, out, E_, E_);
}